// round 1
// baseline (speedup 1.0000x reference)
#include <cuda_runtime.h>
#include <cstdint>

#define N_NODES   100000
#define N_REL     8
#define IN_FEATS  64
#define HD        128          // ATTN_FEATS * NUM_HEADS
#define N_EDGES   800000
#define NEG_SLOPE 0.2f

#define CHUNK 2048             // edges per chunk for k_score
#define TILE  8                // edges per warp-tile

typedef unsigned long long u64;

// ---------------- scratch (static device globals; no allocation) -----------
__device__ float g_p[N_EDGES * 4];        // exp(score) per edge/head (12.8 MB)
__device__ float g_denom[N_NODES * 4];    // softmax denominators (1.6 MB)
__device__ int   g_idx32;                 // 1 if index arrays are int32

// ---------------- small helpers -------------------------------------------
__device__ __forceinline__ u64 pack2(float a, float b) {
    u64 r; asm("mov.b64 %0, {%1,%2};" : "=l"(r) : "f"(a), "f"(b)); return r;
}
__device__ __forceinline__ void unpack2(u64 v, float& a, float& b) {
    asm("mov.b64 {%0,%1}, %2;" : "=f"(a), "=f"(b) : "l"(v));
}
__device__ __forceinline__ u64 fma2(u64 a, u64 b, u64 c) {
    u64 d; asm("fma.rn.f32x2 %0, %1, %2, %3;" : "=l"(d) : "l"(a), "l"(b), "l"(c));
    return d;
}
__device__ __forceinline__ void red4(float* p, float x, float y, float z, float w) {
    asm volatile("red.global.add.v4.f32 [%0], {%1,%2,%3,%4};"
                 :: "l"(p), "f"(x), "f"(y), "f"(z), "f"(w) : "memory");
}
__device__ __forceinline__ long long ldidx(const void* p, int i, int is32) {
    return is32 ? (long long)((const int*)p)[i] : ((const long long*)p)[i];
}
__device__ __forceinline__ float lrelu(float v) {
    return v > 0.0f ? v : NEG_SLOPE * v;
}

// ---------------- kernel 0: detect index dtype -----------------------------
__global__ void k_detect(const void* src) {
    if (threadIdx.x == 0) {
        const long long* p = (const long long*)src;
        int bad = 0;
        #pragma unroll 4
        for (int i = 0; i < 64; i++) {
            long long v = p[i];
            if (v < 0 || v >= N_NODES) bad = 1;   // impossible for true int64 node ids
        }
        g_idx32 = bad;
    }
}

// ---------------- kernel 1: zero output + denominators ---------------------
__global__ void k_zero(float4* out) {
    int i = blockIdx.x * blockDim.x + threadIdx.x;
    const int out4 = N_NODES * HD * 2 / 4;      // 100000*256/4 = 6.4M
    if (i < out4) out[i] = make_float4(0.f, 0.f, 0.f, 0.f);
    if (i < N_NODES * 4 / 4) ((float4*)g_denom)[i] = make_float4(0.f, 0.f, 0.f, 0.f);
}

// ---------------- kernel 2: per-edge score + exp + denom -------------------
// grid = (ceil(E/CHUNK), N_REL); block = 256. Block (c, r) loads W_src[r] and
// W_qual[r] into SMEM, collects edges of relation r in chunk c, processes
// 8 edges per warp-tile with packed f32x2 FMAs.
//
// SMEM layout (bytes):
//   ws    [64*128] f32 : 0      .. 32768
//   wq    [64*128] f32 : 32768  .. 65536
//   bsum  [128]    f32 : 65536  .. 66048
//   attnf [128]    f32 : 66048  .. 66560
//   list  [CHUNK]  i32 : 66560  .. 74752
//   stage [8 warps][2][TILE][64] u64 : 74752 .. 140288   (x duplicated as (v,v))
//   cnt   i32          : 140288 .. 140292
#define SMEM_SCORE_BYTES 140292

extern "C" __global__ void __launch_bounds__(256, 1)
k_score(const float* __restrict__ feat, const float* __restrict__ qual,
        const float* __restrict__ Wsrc, const float* __restrict__ Bsrc,
        const float* __restrict__ Wqual, const float* __restrict__ Bqual,
        const float* __restrict__ attn,
        const void* __restrict__ srcp, const void* __restrict__ dstp,
        const void* __restrict__ rtp, const void* __restrict__ nidp)
{
    extern __shared__ unsigned char sm[];
    float* ws    = (float*)(sm);
    float* wq    = (float*)(sm + 32768);
    float* bsum  = (float*)(sm + 65536);
    float* attnf = (float*)(sm + 66048);
    int*   list  = (int*)  (sm + 66560);
    u64*   stage = (u64*)  (sm + 74752);
    int*   s_cnt = (int*)  (sm + 140288);

    const int r   = blockIdx.y;
    const int c0  = blockIdx.x * CHUNK;
    const int cn  = min(CHUNK, N_EDGES - c0);
    const int tid = threadIdx.x;
    const int is32 = g_idx32;

    // ---- load weights / bias / attn to SMEM ----
    {
        const float4* a = (const float4*)(Wsrc  + r * 64 * HD);
        const float4* b = (const float4*)(Wqual + r * 64 * HD);
        float4* wa = (float4*)ws; float4* wb = (float4*)wq;
        #pragma unroll
        for (int i = tid; i < 64 * HD / 4; i += 256) { wa[i] = a[i]; wb[i] = b[i]; }
        if (tid < HD) {
            bsum[tid]  = Bsrc[r * HD + tid] + Bqual[r * HD + tid];
            attnf[tid] = attn[r * HD + tid];
        }
        if (tid == 0) *s_cnt = 0;
    }
    __syncthreads();

    // ---- collect edges of this relation in this chunk ----
    for (int i = tid; i < cn; i += 256) {
        int e = c0 + i;
        if ((int)ldidx(rtp, e, is32) == r) {
            int p = atomicAdd(s_cnt, 1);
            list[p] = e;
        }
    }
    __syncthreads();
    const int cnt = *s_cnt;
    if (cnt == 0) return;

    const int warp = tid >> 5, lane = tid & 31;
    u64* stF = stage + warp * (2 * TILE * 64);
    u64* stQ = stF + TILE * 64;
    const u64* wsu = (const u64*)ws;
    const u64* wqu = (const u64*)wq;

    const int ntiles = (cnt + TILE - 1) / TILE;
    for (int tile = warp; tile < ntiles; tile += 8) {
        const int base = tile * TILE;

        // ---- stage gathered inputs, duplicated for f32x2 broadcast ----
        int eidx[TILE];
        #pragma unroll
        for (int t = 0; t < TILE; t++) {
            int idx = base + t;
            eidx[t] = (idx < cnt) ? list[idx] : list[base];
        }
        #pragma unroll
        for (int t = 0; t < TILE; t++) {
            int e = eidx[t];
            long long s = ldidx(srcp, e, is32);
            long long q = ldidx(nidp, e, is32);
            float f0 = feat[s * 64 + lane],      f1 = feat[s * 64 + 32 + lane];
            float q0 = qual[q * 64 + lane],      q1 = qual[q * 64 + 32 + lane];
            stF[t * 64 + lane]      = pack2(f0, f0);
            stF[t * 64 + 32 + lane] = pack2(f1, f1);
            stQ[t * 64 + lane]      = pack2(q0, q0);
            stQ[t * 64 + 32 + lane] = pack2(q1, q1);
        }
        __syncwarp();

        // ---- main accumulation: lane owns cols {2l,2l+1} and {2l+64,2l+65} ----
        u64 acc0[TILE], acc1[TILE];
        #pragma unroll
        for (int t = 0; t < TILE; t++) { acc0[t] = 0ULL; acc1[t] = 0ULL; }

        #pragma unroll 8
        for (int k = 0; k < 64; k++) {
            u64 w0 = wsu[k * 64 + lane];
            u64 w1 = wsu[k * 64 + 32 + lane];
            u64 v0 = wqu[k * 64 + lane];
            u64 v1 = wqu[k * 64 + 32 + lane];
            #pragma unroll
            for (int t = 0; t < TILE; t++) {
                u64 xf = stF[t * 64 + k];
                u64 xq = stQ[t * 64 + k];
                acc0[t] = fma2(xf, w0, acc0[t]);
                acc1[t] = fma2(xf, w1, acc1[t]);
                acc0[t] = fma2(xq, v0, acc0[t]);
                acc1[t] = fma2(xq, v1, acc1[t]);
            }
        }

        // ---- epilogue: bias, leaky-relu, attn dot, 16-lane reduce, exp ----
        const int cl = 2 * lane;
        #pragma unroll
        for (int t = 0; t < TILE; t++) {
            float a, b, c, d;
            unpack2(acc0[t], a, b);
            unpack2(acc1[t], c, d);
            float v00 = lrelu(a + bsum[cl]);
            float v01 = lrelu(b + bsum[cl + 1]);
            float v10 = lrelu(c + bsum[cl + 64]);
            float v11 = lrelu(d + bsum[cl + 65]);
            float pl = v00 * attnf[cl]      + v01 * attnf[cl + 1];
            float ph = v10 * attnf[cl + 64] + v11 * attnf[cl + 65];
            #pragma unroll
            for (int off = 8; off; off >>= 1) {
                pl += __shfl_xor_sync(0xffffffffu, pl, off);
                ph += __shfl_xor_sync(0xffffffffu, ph, off);
            }
            if ((lane & 15) == 0 && base + t < cnt) {
                int e = eidx[t];
                int dn = (int)ldidx(dstp, e, is32);
                int h  = lane >> 4;                    // 0 or 1
                float p0 = expf(pl);                   // head h
                float p1 = expf(ph);                   // head h+2
                g_p[e * 4 + h]     = p0;
                g_p[e * 4 + h + 2] = p1;
                atomicAdd(&g_denom[dn * 4 + h],     p0);
                atomicAdd(&g_denom[dn * 4 + h + 2], p1);
            }
        }
        __syncwarp();   // protect stage before next tile's writes
    }
}

// ---------------- kernel 3: normalize + scatter messages -------------------
// 16 lanes per edge; each lane handles one float4 of feat[src], issues 4
// vector reductions (one per head) into ft[dst].
extern "C" __global__ void __launch_bounds__(256)
k_msg(const float* __restrict__ feat,
      const void* __restrict__ srcp, const void* __restrict__ dstp,
      float* __restrict__ out)
{
    const int tid  = threadIdx.x;
    const int half = tid >> 4;
    const int l    = tid & 15;
    const int e    = blockIdx.x * 16 + half;
    if (e >= N_EDGES) return;
    const int is32 = g_idx32;

    long long s = ldidx(srcp, e, is32);
    long long d = ldidx(dstp, e, is32);

    float4 p  = ((const float4*)g_p)[e];
    float4 dn = ((const float4*)g_denom)[(int)d];
    float a0 = p.x / dn.x, a1 = p.y / dn.y, a2 = p.z / dn.z, a3 = p.w / dn.w;

    float4 f = ((const float4*)(feat + s * 64))[l];
    float* base = out + (size_t)d * (4 * IN_FEATS) + l * 4;
    red4(base,                 a0 * f.x, a0 * f.y, a0 * f.z, a0 * f.w);
    red4(base +     IN_FEATS,  a1 * f.x, a1 * f.y, a1 * f.z, a1 * f.w);
    red4(base + 2 * IN_FEATS,  a2 * f.x, a2 * f.y, a2 * f.z, a2 * f.w);
    red4(base + 3 * IN_FEATS,  a3 * f.x, a3 * f.y, a3 * f.z, a3 * f.w);
}

// ---------------- launcher -------------------------------------------------
extern "C" void kernel_launch(void* const* d_in, const int* in_sizes, int n_in,
                              void* d_out, int out_size)
{
    const float* feat  = (const float*)d_in[0];
    const float* qual  = (const float*)d_in[1];
    const float* Wsrc  = (const float*)d_in[2];
    const float* Bsrc  = (const float*)d_in[3];
    const float* Wqual = (const float*)d_in[4];
    const float* Bqual = (const float*)d_in[5];
    const float* attn  = (const float*)d_in[6];
    const void*  src   = d_in[7];
    const void*  dst   = d_in[8];
    const void*  rt    = d_in[9];
    const void*  nid   = d_in[10];
    float* out = (float*)d_out;

    static bool attr_set = false;
    if (!attr_set) {
        cudaFuncSetAttribute(k_score, cudaFuncAttributeMaxDynamicSharedMemorySize,
                             SMEM_SCORE_BYTES);
        attr_set = true;
    }

    k_detect<<<1, 32>>>(src);

    const int out4 = N_NODES * 256 / 4;
    k_zero<<<(out4 + 255) / 256, 256>>>((float4*)out);

    dim3 gscore((N_EDGES + CHUNK - 1) / CHUNK, N_REL);
    k_score<<<gscore, 256, SMEM_SCORE_BYTES>>>(feat, qual, Wsrc, Bsrc, Wqual, Bqual,
                                               attn, src, dst, rt, nid);

    k_msg<<<(N_EDGES + 15) / 16, 256>>>(feat, src, dst, out);
}

// round 3
// speedup vs baseline: 2.4156x; 2.4156x over previous
#include <cuda_runtime.h>
#include <cstdint>

#define N_NODES   100000
#define N_REL     8
#define IN_FEATS  64
#define HD        128
#define N_EDGES   800000
#define NEG_SLOPE 0.2f

#define EPB_HIST  1024
#define NBLK_HIST ((N_EDGES + EPB_HIST - 1) / EPB_HIST)   // 782

typedef unsigned long long u64;
typedef unsigned int u32;

// ---------------- scratch ---------------------------------------------------
__device__ float g_p[N_EDGES * 4];
__device__ float g_denom[N_NODES * 4];
__device__ int   g_idx32;
__device__ int   g_eorder[N_EDGES];
__device__ int   g_bh[NBLK_HIST * 8];
__device__ int   g_boff[NBLK_HIST * 8];
__device__ int   g_roff[9];        // edge offsets per relation
__device__ int   g_woff[9];        // 16-edge warp-tile offsets per relation

// ---------------- helpers ---------------------------------------------------
__device__ __forceinline__ void red4(float* p, float x, float y, float z, float w) {
    asm volatile("red.global.add.v4.f32 [%0], {%1,%2,%3,%4};"
                 :: "l"(p), "f"(x), "f"(y), "f"(z), "f"(w) : "memory");
}
__device__ __forceinline__ long long ldidx(const void* p, int i, int is32) {
    return is32 ? (long long)((const int*)p)[i] : ((const long long*)p)[i];
}
__device__ __forceinline__ float lrelu(float v) { return v > 0.0f ? v : NEG_SLOPE * v; }
__device__ __forceinline__ u32 tf32(float f) {
    u32 r; asm("cvt.rna.tf32.f32 %0, %1;" : "=r"(r) : "f"(f)); return r;
}
__device__ __forceinline__ void mma8(float* d, u32 a0, u32 a1, u32 a2, u32 a3,
                                     u32 b0, u32 b1) {
    asm volatile(
        "mma.sync.aligned.m16n8k8.row.col.f32.tf32.tf32.f32 "
        "{%0,%1,%2,%3}, {%4,%5,%6,%7}, {%8,%9}, {%0,%1,%2,%3};"
        : "+f"(d[0]), "+f"(d[1]), "+f"(d[2]), "+f"(d[3])
        : "r"(a0), "r"(a1), "r"(a2), "r"(a3), "r"(b0), "r"(b1));
}

// ---------------- kernel 0: detect index dtype ------------------------------
__global__ void k_detect(const void* src) {
    if (threadIdx.x == 0) {
        const long long* p = (const long long*)src;
        int bad = 0;
        for (int i = 0; i < 64; i++) {
            long long v = p[i];
            if (v < 0 || v >= N_NODES) bad = 1;
        }
        g_idx32 = bad;
    }
}

// ---------------- kernel 1: zero output + denominators ----------------------
__global__ void k_zero(float4* out) {
    int i = blockIdx.x * blockDim.x + threadIdx.x;
    const int out4 = N_NODES * HD * 2 / 4;
    if (i < out4) out[i] = make_float4(0.f, 0.f, 0.f, 0.f);
    if (i < N_NODES) ((float4*)g_denom)[i] = make_float4(0.f, 0.f, 0.f, 0.f);
}

// ---------------- counting sort by relation ---------------------------------
__global__ void k_hist(const void* __restrict__ rtp) {
    __shared__ int cnt[8];
    int tid = threadIdx.x;
    if (tid < 8) cnt[tid] = 0;
    __syncthreads();
    const int is32 = g_idx32;
    int base = blockIdx.x * EPB_HIST;
    for (int i = tid; i < EPB_HIST; i += 256) {
        int e = base + i;
        if (e < N_EDGES) atomicAdd(&cnt[(int)ldidx(rtp, e, is32)], 1);
    }
    __syncthreads();
    if (tid < 8) g_bh[blockIdx.x * 8 + tid] = cnt[tid];
}

__global__ void k_scan() {
    __shared__ int tot[8];
    int w = threadIdx.x >> 5, lane = threadIdx.x & 31;
    if (w < 8) {
        int running = 0;
        for (int c = 0; c < (NBLK_HIST + 31) / 32; c++) {
            int i = c * 32 + lane;
            int v = (i < NBLK_HIST) ? g_bh[i * 8 + w] : 0;
            int incl = v;
            #pragma unroll
            for (int off = 1; off < 32; off <<= 1) {
                int t = __shfl_up_sync(0xffffffffu, incl, off);
                if (lane >= off) incl += t;
            }
            if (i < NBLK_HIST) g_boff[i * 8 + w] = running + incl - v;
            running += __shfl_sync(0xffffffffu, incl, 31);
        }
        if (lane == 0) tot[w] = running;
    }
    __syncthreads();
    if (threadIdx.x == 0) {
        int ro = 0, wo = 0;
        for (int r = 0; r < 8; r++) {
            g_roff[r] = ro; g_woff[r] = wo;
            ro += tot[r]; wo += (tot[r] + 15) / 16;
        }
        g_roff[8] = ro; g_woff[8] = wo;
    }
}

__global__ void k_scatter(const void* __restrict__ rtp) {
    __shared__ int cur[8];
    int tid = threadIdx.x;
    if (tid < 8) cur[tid] = g_boff[blockIdx.x * 8 + tid] + g_roff[tid];
    __syncthreads();
    const int is32 = g_idx32;
    int base = blockIdx.x * EPB_HIST;
    for (int i = tid; i < EPB_HIST; i += 256) {
        int e = base + i;
        if (e < N_EDGES) {
            int r = (int)ldidx(rtp, e, is32);
            int p = atomicAdd(&cur[r], 1);
            g_eorder[p] = e;
        }
    }
}

// ---------------- kernel 2: mma.sync tf32 score -----------------------------
// SMEM (dynamic):
//   Wp0  [8192] u32 frag-packed Wsrc  : 0      .. 32768
//   Wp1  [8192] u32 frag-packed Wqual : 32768  .. 65536
//   A    [8 warps][16 rows][68] f32   : 65536  .. 100352
//   bsum [128] f32                    : 100352 .. 100864
//   attnf[128] f32                    : 100864 .. 101376
#define OFF_WP0 0
#define OFF_WP1 32768
#define OFF_A   65536
#define OFF_B   100352
#define OFF_AT  100864
#define SMEM_SCORE_BYTES 101376

extern "C" __global__ void __launch_bounds__(256, 2)
k_score(const float* __restrict__ feat, const float* __restrict__ qual,
        const float* __restrict__ Wsrc, const float* __restrict__ Bsrc,
        const float* __restrict__ Wqual, const float* __restrict__ Bqual,
        const float* __restrict__ attn,
        const void* __restrict__ srcp, const void* __restrict__ dstp,
        const void* __restrict__ nidp)
{
    extern __shared__ unsigned char sm[];
    u32*   wp0   = (u32*)(sm + OFF_WP0);
    u32*   wp1   = (u32*)(sm + OFF_WP1);
    float* bsum  = (float*)(sm + OFF_B);
    float* attnf = (float*)(sm + OFF_AT);

    const int tid = threadIdx.x;
    const int wid = tid >> 5, lane = tid & 31;
    const int g = lane >> 2, tg = lane & 3;
    const int is32 = g_idx32;

    u32* As = (u32*)(sm + OFF_A) + wid * (16 * 68);

    int woff[9], roff[9];
    #pragma unroll
    for (int i = 0; i < 9; i++) { woff[i] = g_woff[i]; roff[i] = g_roff[i]; }
    const int totalw = woff[8];
    const int wtpb = (totalw + gridDim.x - 1) / gridDim.x;
    const int wt0 = blockIdx.x * wtpb;
    const int wt1 = min(wt0 + wtpb, totalw);
    if (wt0 >= wt1) return;

    for (int r = 0; r < 8; r++) {
        const int lo = max(wt0, woff[r]);
        const int hi = min(wt1, woff[r + 1]);
        if (lo >= hi) continue;

        // ---- pack weights for relation r into fragment-major SMEM ----
        __syncthreads();
        for (int idx = tid; idx < 8192; idx += 256) {
            int w  = idx & 3;
            int ln = (idx >> 2) & 31;
            int nt = (idx >> 7) & 15;
            int k4 = idx >> 11;
            int k  = 16 * k4 + (ln & 3) + 4 * w;
            int n  = 8 * nt + (ln >> 2);
            wp0[idx] = tf32(Wsrc [(r * 64 + k) * 128 + n]);
            wp1[idx] = tf32(Wqual[(r * 64 + k) * 128 + n]);
        }
        if (tid < 128) {
            bsum[tid]  = Bsrc[r * 128 + tid] + Bqual[r * 128 + tid];
            attnf[tid] = attn[r * 128 + tid];
        }
        __syncthreads();

        const int relend = roff[r + 1];

        for (int wt = lo + wid; wt < hi; wt += 8) {
            const int estart = roff[r] + (wt - woff[r]) * 16;

            float d[16][4];
            #pragma unroll
            for (int nt = 0; nt < 16; nt++)
                #pragma unroll
                for (int j = 0; j < 4; j++) d[nt][j] = 0.f;

            #pragma unroll
            for (int mat = 0; mat < 2; mat++) {
                // ---- gather 16 rows into warp-private slab ----
                {
                    int i = lane >> 1, h = lane & 1;
                    int pos = min(estart + i, relend - 1);
                    int e = g_eorder[pos];
                    long long nd = mat == 0 ? ldidx(srcp, e, is32)
                                            : ldidx(nidp, e, is32);
                    const float4* rp = (const float4*)((mat == 0 ? feat : qual)
                                                       + nd * 64) + h * 8;
                    #pragma unroll
                    for (int j = 0; j < 8; j++) {
                        float4 v = rp[j];
                        uint4 t;
                        t.x = tf32(v.x); t.y = tf32(v.y);
                        t.z = tf32(v.z); t.w = tf32(v.w);
                        *(uint4*)(As + i * 68 + h * 32 + j * 4) = t;
                    }
                }
                __syncwarp();

                // ---- 8 k-steps x 16 n-tiles ----
                const uint4* wp = (const uint4*)(mat == 0 ? wp0 : wp1);
                #pragma unroll
                for (int k4 = 0; k4 < 4; k4++) {
                    int c0 = 16 * k4 + tg;          // k-col for ks = 2*k4
                    u32 a00 = As[g * 68 + c0];
                    u32 a01 = As[(g + 8) * 68 + c0];
                    u32 a02 = As[g * 68 + c0 + 4];
                    u32 a03 = As[(g + 8) * 68 + c0 + 4];
                    u32 a10 = As[g * 68 + c0 + 8];
                    u32 a11 = As[(g + 8) * 68 + c0 + 8];
                    u32 a12 = As[g * 68 + c0 + 12];
                    u32 a13 = As[(g + 8) * 68 + c0 + 12];
                    #pragma unroll
                    for (int nt = 0; nt < 16; nt++) {
                        uint4 b = wp[(k4 * 16 + nt) * 32 + lane];
                        mma8(d[nt], a00, a01, a02, a03, b.x, b.y);
                        mma8(d[nt], a10, a11, a12, a13, b.z, b.w);
                    }
                }
                __syncwarp();
            }

            // ---- epilogue: bias, lrelu, attn-dot, quad reduce, exp ----
            float slo[4] = {0.f, 0.f, 0.f, 0.f};
            float shi[4] = {0.f, 0.f, 0.f, 0.f};
            #pragma unroll
            for (int nt = 0; nt < 16; nt++) {
                int h = nt >> 2;
                int c = 8 * nt + 2 * tg;
                float b0 = bsum[c], b1 = bsum[c + 1];
                float a0 = attnf[c], a1 = attnf[c + 1];
                slo[h] += lrelu(d[nt][0] + b0) * a0 + lrelu(d[nt][1] + b1) * a1;
                shi[h] += lrelu(d[nt][2] + b0) * a0 + lrelu(d[nt][3] + b1) * a1;
            }
            #pragma unroll
            for (int off = 1; off <= 2; off <<= 1) {
                #pragma unroll
                for (int h = 0; h < 4; h++) {
                    slo[h] += __shfl_xor_sync(0xffffffffu, slo[h], off);
                    shi[h] += __shfl_xor_sync(0xffffffffu, shi[h], off);
                }
            }
            if (tg == 0) {
                int plo = estart + g;
                if (plo < relend) {
                    int e = g_eorder[plo];
                    int dn = (int)ldidx(dstp, e, is32);
                    float p0 = expf(slo[0]), p1 = expf(slo[1]);
                    float p2 = expf(slo[2]), p3 = expf(slo[3]);
                    *(float4*)&g_p[e * 4] = make_float4(p0, p1, p2, p3);
                    red4(&g_denom[dn * 4], p0, p1, p2, p3);
                }
                int phi = estart + g + 8;
                if (phi < relend) {
                    int e = g_eorder[phi];
                    int dn = (int)ldidx(dstp, e, is32);
                    float p0 = expf(shi[0]), p1 = expf(shi[1]);
                    float p2 = expf(shi[2]), p3 = expf(shi[3]);
                    *(float4*)&g_p[e * 4] = make_float4(p0, p1, p2, p3);
                    red4(&g_denom[dn * 4], p0, p1, p2, p3);
                }
            }
        }
    }
}

// ---------------- kernel 3: normalize + scatter messages --------------------
extern "C" __global__ void __launch_bounds__(256)
k_msg(const float* __restrict__ feat,
      const void* __restrict__ srcp, const void* __restrict__ dstp,
      float* __restrict__ out)
{
    const int tid  = threadIdx.x;
    const int half = tid >> 4;
    const int l    = tid & 15;
    const int e    = blockIdx.x * 16 + half;
    if (e >= N_EDGES) return;
    const int is32 = g_idx32;

    long long s = ldidx(srcp, e, is32);
    long long d = ldidx(dstp, e, is32);

    float4 p  = ((const float4*)g_p)[e];
    float4 dn = ((const float4*)g_denom)[(int)d];
    float a0 = p.x / dn.x, a1 = p.y / dn.y, a2 = p.z / dn.z, a3 = p.w / dn.w;

    float4 f = ((const float4*)(feat + s * 64))[l];
    float* base = out + (size_t)d * (4 * IN_FEATS) + l * 4;
    red4(base,                a0 * f.x, a0 * f.y, a0 * f.z, a0 * f.w);
    red4(base +     IN_FEATS, a1 * f.x, a1 * f.y, a1 * f.z, a1 * f.w);
    red4(base + 2 * IN_FEATS, a2 * f.x, a2 * f.y, a2 * f.z, a2 * f.w);
    red4(base + 3 * IN_FEATS, a3 * f.x, a3 * f.y, a3 * f.z, a3 * f.w);
}

// ---------------- launcher --------------------------------------------------
extern "C" void kernel_launch(void* const* d_in, const int* in_sizes, int n_in,
                              void* d_out, int out_size)
{
    const float* feat  = (const float*)d_in[0];
    const float* qual  = (const float*)d_in[1];
    const float* Wsrc  = (const float*)d_in[2];
    const float* Bsrc  = (const float*)d_in[3];
    const float* Wqual = (const float*)d_in[4];
    const float* Bqual = (const float*)d_in[5];
    const float* attn  = (const float*)d_in[6];
    const void*  src   = d_in[7];
    const void*  dst   = d_in[8];
    const void*  rt    = d_in[9];
    const void*  nid   = d_in[10];
    float* out = (float*)d_out;

    static bool attr_set = false;
    if (!attr_set) {
        cudaFuncSetAttribute(k_score, cudaFuncAttributeMaxDynamicSharedMemorySize,
                             SMEM_SCORE_BYTES);
        attr_set = true;
    }

    k_detect<<<1, 32>>>(src);

    const int out4 = N_NODES * 256 / 4;
    k_zero<<<(out4 + 255) / 256, 256>>>((float4*)out);

    k_hist<<<NBLK_HIST, 256>>>(rt);
    k_scan<<<1, 256>>>();
    k_scatter<<<NBLK_HIST, 256>>>(rt);

    k_score<<<296, 256, SMEM_SCORE_BYTES>>>(feat, qual, Wsrc, Bsrc, Wqual, Bqual,
                                            attn, src, dst, nid);

    k_msg<<<(N_EDGES + 15) / 16, 256>>>(feat, src, dst, out);
}

// round 4
// speedup vs baseline: 2.7785x; 1.1503x over previous
#include <cuda_runtime.h>
#include <cstdint>

#define N_NODES   100000
#define N_REL     8
#define IN_FEATS  64
#define HD        128
#define N_EDGES   800000
#define NEG_SLOPE 0.2f

#define EPB_HIST  1024
#define NBLK_HIST ((N_EDGES + EPB_HIST - 1) / EPB_HIST)   // 782
#define NB_D      ((N_NODES + 1023) / 1024)               // 98

typedef unsigned long long u64;
typedef unsigned int u32;

// ---------------- scratch ---------------------------------------------------
__device__ float g_p[N_EDGES * 4];
__device__ int   g_idx32;
__device__ int   g_eorder[N_EDGES];      // edges sorted by relation
__device__ int   g_edst[N_EDGES];        // edges sorted by dst
__device__ int   g_relcnt[8];
__device__ int   g_relcur[8];
__device__ int   g_roff[9];
__device__ int   g_woff[9];
__device__ int   g_dstcnt[N_NODES];
__device__ int   g_rowoff[N_NODES + 1];
__device__ int   g_dstcur[N_NODES];
__device__ int   g_bsumd[128];

// ---------------- helpers ---------------------------------------------------
__device__ __forceinline__ long long ldidx(const void* p, int i, int is32) {
    return is32 ? (long long)((const int*)p)[i] : ((const long long*)p)[i];
}
__device__ __forceinline__ float lrelu(float v) { return v > 0.0f ? v : NEG_SLOPE * v; }
__device__ __forceinline__ u32 tf32(float f) {
    u32 r; asm("cvt.rna.tf32.f32 %0, %1;" : "=r"(r) : "f"(f)); return r;
}
__device__ __forceinline__ void mma8(float* d, u32 a0, u32 a1, u32 a2, u32 a3,
                                     u32 b0, u32 b1) {
    asm volatile(
        "mma.sync.aligned.m16n8k8.row.col.f32.tf32.tf32.f32 "
        "{%0,%1,%2,%3}, {%4,%5,%6,%7}, {%8,%9}, {%0,%1,%2,%3};"
        : "+f"(d[0]), "+f"(d[1]), "+f"(d[2]), "+f"(d[3])
        : "r"(a0), "r"(a1), "r"(a2), "r"(a3), "r"(b0), "r"(b1));
}

// ---------------- kernel: detect index dtype --------------------------------
__global__ void k_detect(const void* src) {
    if (threadIdx.x == 0) {
        const long long* p = (const long long*)src;
        int bad = 0;
        for (int i = 0; i < 64; i++) {
            long long v = p[i];
            if (v < 0 || v >= N_NODES) bad = 1;
        }
        g_idx32 = bad;
    }
}

// ---------------- kernel: zero sort scratch ---------------------------------
__global__ void k_zinit() {
    int i = blockIdx.x * blockDim.x + threadIdx.x;
    if (i < N_NODES) g_dstcnt[i] = 0;
    if (i < 8) g_relcnt[i] = 0;
}

// ---------------- kernel: fused histogram (relation + dst) ------------------
__global__ void k_hist(const void* __restrict__ rtp, const void* __restrict__ dstp) {
    __shared__ int cnt[8];
    int tid = threadIdx.x;
    if (tid < 8) cnt[tid] = 0;
    __syncthreads();
    const int is32 = g_idx32;
    int base = blockIdx.x * EPB_HIST;
    for (int i = tid; i < EPB_HIST; i += 256) {
        int e = base + i;
        if (e < N_EDGES) {
            atomicAdd(&cnt[(int)ldidx(rtp, e, is32)], 1);
            atomicAdd(&g_dstcnt[(int)ldidx(dstp, e, is32)], 1);
        }
    }
    __syncthreads();
    if (tid < 8) atomicAdd(&g_relcnt[tid], cnt[tid]);
}

// ---------------- kernel: tiny relation scan --------------------------------
__global__ void k_rscan() {
    if (threadIdx.x == 0) {
        int ro = 0, wo = 0;
        for (int r = 0; r < 8; r++) {
            int c = g_relcnt[r];
            g_roff[r] = ro; g_relcur[r] = ro; g_woff[r] = wo;
            ro += c; wo += (c + 15) / 16;
        }
        g_roff[8] = ro; g_woff[8] = wo;
    }
}

// ---------------- dst prefix scan (3 kernels) -------------------------------
__global__ void k_dscan1() {
    __shared__ int ws[32];
    int t = threadIdx.x, b = blockIdx.x;
    int i = b * 1024 + t;
    int v = (i < N_NODES) ? g_dstcnt[i] : 0;
    int lane = t & 31, w = t >> 5;
    int x = v;
    #pragma unroll
    for (int o = 1; o < 32; o <<= 1) {
        int y = __shfl_up_sync(0xffffffffu, x, o);
        if (lane >= o) x += y;
    }
    if (lane == 31) ws[w] = x;
    __syncthreads();
    if (t < 32) {
        int y = ws[t];
        #pragma unroll
        for (int o = 1; o < 32; o <<= 1) {
            int z = __shfl_up_sync(0xffffffffu, y, o);
            if (t >= o) y += z;
        }
        ws[t] = y;
    }
    __syncthreads();
    int excl = x - v + (w ? ws[w - 1] : 0);
    if (i < N_NODES) g_rowoff[i] = excl;
    if (t == 1023) g_bsumd[b] = excl + v;
}

__global__ void k_dscan2() {
    __shared__ int ws[4];
    int t = threadIdx.x;            // 128 threads
    int v = (t < NB_D) ? g_bsumd[t] : 0;
    int lane = t & 31, w = t >> 5;
    int x = v;
    #pragma unroll
    for (int o = 1; o < 32; o <<= 1) {
        int y = __shfl_up_sync(0xffffffffu, x, o);
        if (lane >= o) x += y;
    }
    if (lane == 31) ws[w] = x;
    __syncthreads();
    if (t < 4) {
        int y = ws[t];
        for (int o = 1; o < 4; o <<= 1) {
            int z = __shfl_up_sync(0x0000000fu, y, o);
            if (t >= o) y += z;
        }
        ws[t] = y;
    }
    __syncthreads();
    int excl = x - v + (w ? ws[w - 1] : 0);
    if (t < NB_D) g_bsumd[t] = excl;
}

__global__ void k_dscan3() {
    int t = threadIdx.x, b = blockIdx.x;
    int i = b * 1024 + t;
    if (i < N_NODES) {
        int v = g_rowoff[i] + g_bsumd[b];
        g_rowoff[i] = v;
        g_dstcur[i] = v;
    }
    if (i == 0) g_rowoff[N_NODES] = N_EDGES;
}

// ---------------- kernel: fused scatter (relation + dst) --------------------
__global__ void k_scatter(const void* __restrict__ rtp, const void* __restrict__ dstp) {
    __shared__ int cnt[8], base[8];
    int tid = threadIdx.x;
    if (tid < 8) cnt[tid] = 0;
    __syncthreads();
    const int is32 = g_idx32;
    int b0 = blockIdx.x * EPB_HIST;
    int rloc[4];
    #pragma unroll
    for (int c = 0; c < 4; c++) {
        int e = b0 + c * 256 + tid;
        rloc[c] = -1;
        if (e < N_EDGES) {
            rloc[c] = (int)ldidx(rtp, e, is32);
            atomicAdd(&cnt[rloc[c]], 1);
            int d = (int)ldidx(dstp, e, is32);
            int pos = atomicAdd(&g_dstcur[d], 1);
            g_edst[pos] = e;
        }
    }
    __syncthreads();
    if (tid < 8) { base[tid] = atomicAdd(&g_relcur[tid], cnt[tid]); cnt[tid] = 0; }
    __syncthreads();
    #pragma unroll
    for (int c = 0; c < 4; c++) {
        if (rloc[c] >= 0) {
            int pos = base[rloc[c]] + atomicAdd(&cnt[rloc[c]], 1);
            g_eorder[pos] = b0 + c * 256 + tid;
        }
    }
}

// ---------------- kernel: mma.sync tf32 score -------------------------------
#define OFF_WP0 0
#define OFF_WP1 32768
#define OFF_A   65536
#define OFF_B   100352
#define OFF_AT  100864
#define SMEM_SCORE_BYTES 101376

extern "C" __global__ void __launch_bounds__(256, 2)
k_score(const float* __restrict__ feat, const float* __restrict__ qual,
        const float* __restrict__ Wsrc, const float* __restrict__ Bsrc,
        const float* __restrict__ Wqual, const float* __restrict__ Bqual,
        const float* __restrict__ attn,
        const void* __restrict__ srcp, const void* __restrict__ nidp)
{
    extern __shared__ unsigned char sm[];
    u32*   wp0   = (u32*)(sm + OFF_WP0);
    u32*   wp1   = (u32*)(sm + OFF_WP1);
    float* bsum  = (float*)(sm + OFF_B);
    float* attnf = (float*)(sm + OFF_AT);

    const int tid = threadIdx.x;
    const int wid = tid >> 5, lane = tid & 31;
    const int g = lane >> 2, tg = lane & 3;
    const int is32 = g_idx32;

    u32* As = (u32*)(sm + OFF_A) + wid * (16 * 68);

    int woff[9], roff[9];
    #pragma unroll
    for (int i = 0; i < 9; i++) { woff[i] = g_woff[i]; roff[i] = g_roff[i]; }
    const int totalw = woff[8];
    const int wtpb = (totalw + gridDim.x - 1) / gridDim.x;
    const int wt0 = blockIdx.x * wtpb;
    const int wt1 = min(wt0 + wtpb, totalw);
    if (wt0 >= wt1) return;

    for (int r = 0; r < 8; r++) {
        const int lo = max(wt0, woff[r]);
        const int hi = min(wt1, woff[r + 1]);
        if (lo >= hi) continue;

        __syncthreads();
        for (int idx = tid; idx < 8192; idx += 256) {
            int w  = idx & 3;
            int ln = (idx >> 2) & 31;
            int nt = (idx >> 7) & 15;
            int k4 = idx >> 11;
            int k  = 16 * k4 + (ln & 3) + 4 * w;
            int n  = 8 * nt + (ln >> 2);
            wp0[idx] = tf32(Wsrc [(r * 64 + k) * 128 + n]);
            wp1[idx] = tf32(Wqual[(r * 64 + k) * 128 + n]);
        }
        if (tid < 128) {
            bsum[tid]  = Bsrc[r * 128 + tid] + Bqual[r * 128 + tid];
            attnf[tid] = attn[r * 128 + tid];
        }
        __syncthreads();

        const int relend = roff[r + 1];

        for (int wt = lo + wid; wt < hi; wt += 8) {
            const int estart = roff[r] + (wt - woff[r]) * 16;

            float d[16][4];
            #pragma unroll
            for (int nt = 0; nt < 16; nt++)
                #pragma unroll
                for (int j = 0; j < 4; j++) d[nt][j] = 0.f;

            #pragma unroll
            for (int mat = 0; mat < 2; mat++) {
                {
                    int i = lane >> 1, h = lane & 1;
                    int pos = min(estart + i, relend - 1);
                    int e = g_eorder[pos];
                    long long nd = mat == 0 ? ldidx(srcp, e, is32)
                                            : ldidx(nidp, e, is32);
                    const float4* rp = (const float4*)((mat == 0 ? feat : qual)
                                                       + nd * 64) + h * 8;
                    #pragma unroll
                    for (int j = 0; j < 8; j++) {
                        float4 v = rp[j];
                        uint4 t;
                        t.x = tf32(v.x); t.y = tf32(v.y);
                        t.z = tf32(v.z); t.w = tf32(v.w);
                        *(uint4*)(As + i * 68 + h * 32 + j * 4) = t;
                    }
                }
                __syncwarp();

                const uint4* wp = (const uint4*)(mat == 0 ? wp0 : wp1);
                #pragma unroll
                for (int k4 = 0; k4 < 4; k4++) {
                    int c0 = 16 * k4 + tg;
                    u32 a00 = As[g * 68 + c0];
                    u32 a01 = As[(g + 8) * 68 + c0];
                    u32 a02 = As[g * 68 + c0 + 4];
                    u32 a03 = As[(g + 8) * 68 + c0 + 4];
                    u32 a10 = As[g * 68 + c0 + 8];
                    u32 a11 = As[(g + 8) * 68 + c0 + 8];
                    u32 a12 = As[g * 68 + c0 + 12];
                    u32 a13 = As[(g + 8) * 68 + c0 + 12];
                    #pragma unroll
                    for (int nt = 0; nt < 16; nt++) {
                        uint4 b = wp[(k4 * 16 + nt) * 32 + lane];
                        mma8(d[nt], a00, a01, a02, a03, b.x, b.y);
                        mma8(d[nt], a10, a11, a12, a13, b.z, b.w);
                    }
                }
                __syncwarp();
            }

            float slo[4] = {0.f, 0.f, 0.f, 0.f};
            float shi[4] = {0.f, 0.f, 0.f, 0.f};
            #pragma unroll
            for (int nt = 0; nt < 16; nt++) {
                int h = nt >> 2;
                int c = 8 * nt + 2 * tg;
                float b0 = bsum[c], b1 = bsum[c + 1];
                float a0 = attnf[c], a1 = attnf[c + 1];
                slo[h] += lrelu(d[nt][0] + b0) * a0 + lrelu(d[nt][1] + b1) * a1;
                shi[h] += lrelu(d[nt][2] + b0) * a0 + lrelu(d[nt][3] + b1) * a1;
            }
            #pragma unroll
            for (int off = 1; off <= 2; off <<= 1) {
                #pragma unroll
                for (int h = 0; h < 4; h++) {
                    slo[h] += __shfl_xor_sync(0xffffffffu, slo[h], off);
                    shi[h] += __shfl_xor_sync(0xffffffffu, shi[h], off);
                }
            }
            if (tg == 0) {
                int plo = estart + g;
                if (plo < relend) {
                    int e = g_eorder[plo];
                    *(float4*)&g_p[e * 4] = make_float4(expf(slo[0]), expf(slo[1]),
                                                        expf(slo[2]), expf(slo[3]));
                }
                int phi = estart + g + 8;
                if (phi < relend) {
                    int e = g_eorder[phi];
                    *(float4*)&g_p[e * 4] = make_float4(expf(shi[0]), expf(shi[1]),
                                                        expf(shi[2]), expf(shi[3]));
                }
            }
        }
    }
}

// ---------------- kernel: per-node CSR aggregation --------------------------
extern "C" __global__ void __launch_bounds__(256)
k_agg(const float* __restrict__ feat, const void* __restrict__ srcp,
      float* __restrict__ out)
{
    const int n = (blockIdx.x * 256 + threadIdx.x) >> 5;   // node id
    const int lane = threadIdx.x & 31;
    if (n >= N_NODES) return;
    const int is32 = g_idx32;

    const int beg = g_rowoff[n], end = g_rowoff[n + 1];

    float a00 = 0.f, a01 = 0.f, a10 = 0.f, a11 = 0.f;
    float a20 = 0.f, a21 = 0.f, a30 = 0.f, a31 = 0.f;
    float d0 = 0.f, d1 = 0.f, d2 = 0.f, d3 = 0.f;

    // software-pipelined edge loop (prefetch edge id + src index)
    int e  = (beg < end) ? g_edst[beg] : 0;
    long long s = (beg < end) ? ldidx(srcp, e, is32) : 0;
    for (int i = beg; i < end; i++) {
        int e_n = (i + 1 < end) ? g_edst[i + 1] : 0;
        float4 p  = *(const float4*)&g_p[e * 4];
        float2 f  = *(const float2*)&feat[s * 64 + 2 * lane];
        long long s_n = (i + 1 < end) ? ldidx(srcp, e_n, is32) : 0;
        a00 += p.x * f.x; a01 += p.x * f.y; d0 += p.x;
        a10 += p.y * f.x; a11 += p.y * f.y; d1 += p.y;
        a20 += p.z * f.x; a21 += p.z * f.y; d2 += p.z;
        a30 += p.w * f.x; a31 += p.w * f.y; d3 += p.w;
        e = e_n; s = s_n;
    }

    float i0 = d0 > 0.f ? __frcp_rn(d0) : 0.f;
    float i1 = d1 > 0.f ? __frcp_rn(d1) : 0.f;
    float i2 = d2 > 0.f ? __frcp_rn(d2) : 0.f;
    float i3 = d3 > 0.f ? __frcp_rn(d3) : 0.f;

    float* o = out + (size_t)n * 256 + 2 * lane;
    *(float2*)(o)       = make_float2(a00 * i0, a01 * i0);
    *(float2*)(o + 64)  = make_float2(a10 * i1, a11 * i1);
    *(float2*)(o + 128) = make_float2(a20 * i2, a21 * i2);
    *(float2*)(o + 192) = make_float2(a30 * i3, a31 * i3);
}

// ---------------- launcher --------------------------------------------------
extern "C" void kernel_launch(void* const* d_in, const int* in_sizes, int n_in,
                              void* d_out, int out_size)
{
    const float* feat  = (const float*)d_in[0];
    const float* qual  = (const float*)d_in[1];
    const float* Wsrc  = (const float*)d_in[2];
    const float* Bsrc  = (const float*)d_in[3];
    const float* Wqual = (const float*)d_in[4];
    const float* Bqual = (const float*)d_in[5];
    const float* attn  = (const float*)d_in[6];
    const void*  src   = d_in[7];
    const void*  dst   = d_in[8];
    const void*  rt    = d_in[9];
    const void*  nid   = d_in[10];
    float* out = (float*)d_out;

    static bool attr_set = false;
    if (!attr_set) {
        cudaFuncSetAttribute(k_score, cudaFuncAttributeMaxDynamicSharedMemorySize,
                             SMEM_SCORE_BYTES);
        attr_set = true;
    }

    k_detect<<<1, 32>>>(src);
    k_zinit<<<(N_NODES + 255) / 256, 256>>>();
    k_hist<<<NBLK_HIST, 256>>>(rt, dst);
    k_rscan<<<1, 32>>>();
    k_dscan1<<<NB_D, 1024>>>();
    k_dscan2<<<1, 128>>>();
    k_dscan3<<<NB_D, 1024>>>();
    k_scatter<<<NBLK_HIST, 256>>>(rt, dst);

    k_score<<<296, 256, SMEM_SCORE_BYTES>>>(feat, qual, Wsrc, Bsrc, Wqual, Bqual,
                                            attn, src, nid);

    k_agg<<<(N_NODES * 32 + 255) / 256, 256>>>(feat, src, out);
}